// round 16
// baseline (speedup 1.0000x reference)
#include <cuda_runtime.h>
#include <math.h>

#define V 720
#define QV 180
#define U 736
#define NXY 512
#define NPIX (NXY * NXY)
#define NTAPS 368

#define DU_D   1.2858
#define DSO_D  595.0
#define DOD_D  490.6
#define DSD_D  (DSO_D + DOD_D)
#define SVOX_D 400.0
#define PI_D   3.14159265358979323846

// parity-packed conv arrays
#define PADE 380
#define PODD 383
#define WLEN 1124

// guard-band padded filtered rows: slot i holds detector index u = i - QPAD
#define QPAD 512
#define QSTRIDE 1760            // 512 + 736 + 512

// ---- device-global scratch ----
__device__ float4 g_trig[V];             // (cb*DSD/DU, sb*DSD/DU, cb, sb)
// planar (A,B) per view: row v occupies [v*2*QSTRIDE, ...): A plane then B plane.
// A[s]=Q[s], B[s]=Q[s+1]-Q[s] for s in [0,U-2]; (0,0) outside -> exact masking.
__device__ float g_QAB[V * 2 * QSTRIDE];
__device__ float g_accS[NPIX];           // views   0..179 -> pixel P
__device__ float g_acc90[NPIX];          // views 180..359 -> rot90(P)
__device__ float g_acc180[NPIX];         // views 360..539 -> -P
__device__ float g_acc270[NPIX];         // views 540..719 -> rot270(P)

// ---------------------------------------------------------------------------
// Kernel 1: cosine weight + Ram-Lak conv, parity-packed + register-tiled,
// split left/right tap loops bounded per warp (skip guaranteed-zero taps).
// ---------------------------------------------------------------------------
__global__ __launch_bounds__(192) void filter_kernel(const float* __restrict__ sino) {
    __shared__ __align__(16) float wo_s[WLEN];
    __shared__ __align__(16) float we_s[WLEN];
    __shared__ __align__(16) float ho_s[NTAPS];
    __shared__ float qrow[U];

    const int v = blockIdx.x;
    const int tid = threadIdx.x;

    for (int i = tid; i < WLEN; i += 192) { wo_s[i] = 0.0f; we_s[i] = 0.0f; }
    for (int k = tid; k < NTAPS; k += 192) {
        float d = (float)(PI_D * DU_D) * (float)(2 * k + 1);
        ho_s[k] = -1.0f / (d * d);
    }
    if (tid == 0) {
        float bf = (float)(2.0 * PI_D * (double)v / (double)V);
        float cb = (float)cos((double)bf);
        float sb = (float)sin((double)bf);
        float kk = (float)(DSD_D / DU_D);
        g_trig[v] = make_float4(cb * kk, sb * kk, cb, sb);
    }
    __syncthreads();

    {
        const float* row = sino + v * U;
        const float dsd  = (float)DSD_D;
        const float dsd2 = (float)(DSD_D * DSD_D);
        const float du   = (float)DU_D;
        for (int u = tid; u < U; u += 192) {
            float us = ((float)u - 367.5f) * du;
            float w = row[u] * (dsd * rsqrtf(dsd2 + us * us));
            if (u & 1) wo_s[PADE + (u >> 1)] = w;
            else       we_s[PODD + (u >> 1)] = w;
        }
    }
    __syncthreads();

    const int grp = tid / 96;
    const int t   = tid % 96;
    const int wi  = t >> 5;                 // warp-chunk index 0..2 (uniform/warp)
    if (t < 92) {
        const int b = 4 * t;
        const float* A = grp ? (we_s + PODD + 1) : (wo_s + PADE);
        const float* C = grp ? (wo_s + PADE)     : (we_s + PODD);
        const float h0 = (float)(1.0 / (4.0 * DU_D * DU_D));

        float acc0 = h0 * C[b + 0];
        float acc1 = h0 * C[b + 1];
        float acc2 = h0 * C[b + 2];
        float acc3 = h0 * C[b + 3];

        const int JL = min(32 * wi + 32, 92);
        const int JR = 92 - 32 * wi;

        {
            float4 Llo = *(const float4*)(A + b - 4);
            float4 Lhi = *(const float4*)(A + b);
            #pragma unroll 4
            for (int j = 0; j < JL; j++) {
                float4 h4 = *(const float4*)(ho_s + 4 * j);
                acc0 += h4.x * Llo.w;
                acc1 += h4.x * Lhi.x;
                acc2 += h4.x * Lhi.y;
                acc3 += h4.x * Lhi.z;
                acc0 += h4.y * Llo.z;
                acc1 += h4.y * Llo.w;
                acc2 += h4.y * Lhi.x;
                acc3 += h4.y * Lhi.y;
                acc0 += h4.z * Llo.y;
                acc1 += h4.z * Llo.z;
                acc2 += h4.z * Llo.w;
                acc3 += h4.z * Lhi.x;
                acc0 += h4.w * Llo.x;
                acc1 += h4.w * Llo.y;
                acc2 += h4.w * Llo.z;
                acc3 += h4.w * Llo.w;
                Lhi = Llo;
                Llo = *(const float4*)(A + b - 4 * j - 8);
            }
        }
        {
            float4 rlo = *(const float4*)(A + b);
            float4 rhi = *(const float4*)(A + b + 4);
            #pragma unroll 4
            for (int j = 0; j < JR; j++) {
                float4 h4 = *(const float4*)(ho_s + 4 * j);
                acc0 += h4.x * rlo.x;
                acc1 += h4.x * rlo.y;
                acc2 += h4.x * rlo.z;
                acc3 += h4.x * rlo.w;
                acc0 += h4.y * rlo.y;
                acc1 += h4.y * rlo.z;
                acc2 += h4.y * rlo.w;
                acc3 += h4.y * rhi.x;
                acc0 += h4.z * rlo.z;
                acc1 += h4.z * rlo.w;
                acc2 += h4.z * rhi.x;
                acc3 += h4.z * rhi.y;
                acc0 += h4.w * rlo.w;
                acc1 += h4.w * rhi.x;
                acc2 += h4.w * rhi.y;
                acc3 += h4.w * rhi.z;
                rlo = rhi;
                rhi = *(const float4*)(A + b + 4 * j + 8);
            }
        }

        const float du = (float)DU_D;
        const int u0 = 8 * t + grp;
        qrow[u0 + 0] = du * acc0;
        qrow[u0 + 2] = du * acc1;
        qrow[u0 + 4] = du * acc2;
        qrow[u0 + 6] = du * acc3;
    }
    __syncthreads();

    // planar A/B planes for this view; (0,0) outside [0, U-2] = exact masking
    {
        float* dstA = g_QAB + (size_t)v * 2 * QSTRIDE;
        float* dstB = dstA + QSTRIDE;
        for (int i = tid; i < QSTRIDE; i += 192) {
            int s = i - QPAD;
            bool in = (s >= 0) && (s <= U - 2);
            float q0 = in ? qrow[s] : 0.0f;
            float q1 = in ? qrow[s + 1] : 0.0f;
            dstA[i] = q0;
            dstB[i] = q1 - q0;
        }
    }
}

// ---------------------------------------------------------------------------
// Kernel 2: 4-fold symmetric backprojection over views 0..179.
// One geometry eval -> 4 accumulations from view rows v, v+180, v+360, v+540.
// Planar A/B split: 8 scattered LDG.32 (1-2 wf each, cross-LDG rate) replace
// 4 LDG.64 (2-wf floor each at within-LDG replay rate).
// All 8 offsets are compile-time immediates off one computed address.
// ---------------------------------------------------------------------------
#define M23 8388608.0f                         // 2^23
#define ADDR_BIAS (0x4B000000ULL * 4ULL)       // magic-float bias * 4 B/slot
#define ABOFF ((unsigned long long)QSTRIDE * 4ULL)   // A->B plane, 7040 B
#define VROWB ((unsigned long long)QSTRIDE * 8ULL)   // per-view (A+B), 14080 B
#define QB (180ULL * VROWB)                    // quadrant stride, 2,534,400 B

__global__ __launch_bounds__(256, 4) void bp_kernel() {
    __shared__ __align__(16) float4 strig[QV];

    const int tid = threadIdx.y * 32 + threadIdx.x;
    for (int i = tid; i < QV; i += 256) strig[i] = g_trig[i];
    __syncthreads();

    const int iy = blockIdx.x * 32 + threadIdx.x;
    const int ix = blockIdx.y * 8 + threadIdx.y;

    const float dx  = (float)(SVOX_D / (double)NXY);
    const float y   = ((float)iy - 255.5f) * dx;
    const float x   = ((float)ix - 255.5f) * dx;
    const float c0  = 367.5f + (float)QPAD;
    const float dso = (float)DSO_D;

    unsigned long long pa = (unsigned long long)(const char*)g_QAB - ADDR_BIAS;

    float accS = 0.0f, acc90 = 0.0f, acc180 = 0.0f, acc270 = 0.0f;

    #pragma unroll 4
    for (int v = 0; v < QV; v++, pa += VROWB) {
        float4 tg = strig[v];

        float t = fmaf(x, tg.x, y * tg.y);
        float D = fmaf(x, tg.w, fmaf(-y, tg.z, dso));
        float r;
        asm("rcp.approx.f32 %0, %1;" : "=f"(r) : "f"(D));
        float idx = fmaf(t, r, c0);
        float m = __fadd_rd(idx, M23);

        const char* a = (const char*)(pa + (unsigned long long)__float_as_uint(m) * 4ULL);
        float A0 = __ldg((const float*)(a));
        float B0 = __ldg((const float*)(a + ABOFF));
        float A1 = __ldg((const float*)(a + QB));
        float B1 = __ldg((const float*)(a + QB + ABOFF));
        float A2 = __ldg((const float*)(a + 2ULL * QB));
        float B2 = __ldg((const float*)(a + 2ULL * QB + ABOFF));
        float A3 = __ldg((const float*)(a + 3ULL * QB));
        float B3 = __ldg((const float*)(a + 3ULL * QB + ABOFF));

        float f = idx - (m - M23);
        float w = r * r;

        accS   = fmaf(fmaf(f, B0, A0), w, accS);
        acc90  = fmaf(fmaf(f, B1, A1), w, acc90);
        acc180 = fmaf(fmaf(f, B2, A2), w, acc180);
        acc270 = fmaf(fmaf(f, B3, A3), w, acc270);
    }

    const int p = ix * NXY + iy;
    g_accS[p]   = accS;
    g_acc90[p]  = acc90;
    g_acc180[p] = acc180;
    g_acc270[p] = acc270;
}

// ---------------------------------------------------------------------------
// Kernel 3: combine. For output O=(ix,iy):
//   out[O] = scale * ( S[O] + acc90[rot270(O)] + acc180[-O] + acc270[rot90(O)] )
// ---------------------------------------------------------------------------
__global__ __launch_bounds__(256) void combine_kernel(float* __restrict__ out) {
    const int i = blockIdx.x * 256 + threadIdx.x;
    const int ix = i >> 9;
    const int iy = i & 511;
    const float scale = (float)(0.5 * (2.0 * PI_D / (double)V) * DSO_D * DSO_D);

    float s   = g_accS[i];
    float a18 = g_acc180[NPIX - 1 - i];
    float a9  = g_acc90[iy * NXY + (NXY - 1 - ix)];    // P = rot270(O)
    float a27 = g_acc270[(NXY - 1 - iy) * NXY + ix];   // P = rot90(O)

    out[i] = (s + a9 + a18 + a27) * scale;
}

// ---------------------------------------------------------------------------
extern "C" void kernel_launch(void* const* d_in, const int* in_sizes, int n_in,
                              void* d_out, int out_size) {
    (void)in_sizes; (void)n_in; (void)out_size;
    const float* sino = (const float*)d_in[0];
    float* out = (float*)d_out;

    filter_kernel<<<V, 192>>>(sino);
    dim3 bpBlock(32, 8);
    dim3 bpGrid(NXY / 32, NXY / 8);     // 16 x 64 = 1024 blocks
    bp_kernel<<<bpGrid, bpBlock>>>();
    combine_kernel<<<NPIX / 256, 256>>>(out);
}